// round 1
// baseline (speedup 1.0000x reference)
#include <cuda_runtime.h>
#include <cstdint>

#define B_ 8
#define N_ 50000
#define P_TOTAL (B_*N_)     // 400000
#define H_ 64
#define CD 64
#define TD 512
#define NB_ 5
#define OUT_ 12
#define CCD (CD+TD)         // 576

// Precomputed task-feature contribution: tfb[b][i][j] = fc_c_b[i][j] + task[b] @ fc_c_W[i][64:,:]
__device__ float g_tfb[B_*NB_*H_];

// ---------------- packed f32x2 helpers ----------------
union F2 {
    float2 f;
    unsigned long long u;
};

__device__ __forceinline__ void ffma2(F2& d, const F2& a, const F2& b) {
    asm("fma.rn.f32x2 %0, %1, %2, %0;" : "+l"(d.u) : "l"(a.u), "l"(b.u));
}
__device__ __forceinline__ F2 dup2(float w) {
    F2 r; asm("mov.b64 %0, {%1, %1};" : "=l"(r.u) : "f"(w)); return r;
}
__device__ __forceinline__ F2 relu2(F2 v) {
    v.f.x = fmaxf(v.f.x, 0.f);
    v.f.y = fmaxf(v.f.y, 0.f);
    return v;
}

// ---------------- tfb precompute ----------------
__global__ void tfb_kernel(const float* __restrict__ task,   // [B,512]
                           const float* __restrict__ fcW,    // [NB,576,64]
                           const float* __restrict__ fcb)    // [NB,64]
{
    int blk = blockIdx.x;            // b*NB + i
    int b = blk / NB_, i = blk % NB_;
    int j = threadIdx.x;
    float acc = fcb[i*H_ + j];
    const float* w = fcW + ((size_t)i*CCD + CD)*H_ + j;
    const float* t = task + (size_t)b*TD;
    #pragma unroll 8
    for (int k = 0; k < TD; ++k)
        acc += t[k] * w[(size_t)k*H_];
    g_tfb[(b*NB_ + i)*H_ + j] = acc;
}

// ---------------- main kernel ----------------
// SMEM small-param offsets (floats)
#define SM_WP   0        // fc_p_W [3][64]
#define SM_BP   192      // fc_p_b [64]
#define SM_B0   256      // blk0_b [5][64]
#define SM_B1   576      // blk1_b [5][64]
#define SM_WOUT 896      // fc_out_W [64][12]
#define SM_BOUT 1664     // fc_out_b [12]
#define SM_SMALL_N 1676

#define SMEM_BYTES (64*64*8 /*c_s*/ + 64*64*8 /*act_s*/ + 64*64*4 /*w_s*/ + SM_SMALL_N*4)

// Copy one 64x64 fp32 weight matrix (k-major, same as global layout) into w_s.
__device__ __forceinline__ void copy_w(float* w_s, const float* __restrict__ src, int tid) {
    const float4* s4 = (const float4*)src;
    float4* d4 = (float4*)w_s;
    #pragma unroll
    for (int r = 0; r < 4; ++r)
        d4[tid + 256*r] = s4[tid + 256*r];
}

// One 128pts x 64out x 64k GEMM. Input activations packed [k][pair] float2 in smem.
// Thread accumulates 8 outputs for pairs px (acc0) and px+32 (acc1).
__device__ __forceinline__ void gemm64(const float2* __restrict__ in, const float* __restrict__ w,
                                       int px, int jbase, F2 acc0[8], F2 acc1[8])
{
    #pragma unroll
    for (int jj = 0; jj < 8; ++jj) { acc0[jj].u = 0ULL; acc1[jj].u = 0ULL; }
    #pragma unroll 4
    for (int k = 0; k < 64; ++k) {
        F2 a0, a1;
        a0.f = in[k*64 + px];
        a1.f = in[k*64 + px + 32];
        const float4* wr = (const float4*)(w + k*64 + jbase);  // warp-uniform -> LDS broadcast
        float4 w0 = wr[0], w1 = wr[1];
        F2 pk;
        pk = dup2(w0.x); ffma2(acc0[0], a0, pk); ffma2(acc1[0], a1, pk);
        pk = dup2(w0.y); ffma2(acc0[1], a0, pk); ffma2(acc1[1], a1, pk);
        pk = dup2(w0.z); ffma2(acc0[2], a0, pk); ffma2(acc1[2], a1, pk);
        pk = dup2(w0.w); ffma2(acc0[3], a0, pk); ffma2(acc1[3], a1, pk);
        pk = dup2(w1.x); ffma2(acc0[4], a0, pk); ffma2(acc1[4], a1, pk);
        pk = dup2(w1.y); ffma2(acc0[5], a0, pk); ffma2(acc1[5], a1, pk);
        pk = dup2(w1.z); ffma2(acc0[6], a0, pk); ffma2(acc1[6], a1, pk);
        pk = dup2(w1.w); ffma2(acc0[7], a0, pk); ffma2(acc1[7], a1, pk);
    }
}

__global__ void __launch_bounds__(256, 2)
decoder_kernel(const float* __restrict__ p,        // [P,3]
               const float* __restrict__ c,        // [P,64]
               const float* __restrict__ fc_p_W,   // [3,64]
               const float* __restrict__ fc_p_b,   // [64]
               const float* __restrict__ fc_c_W,   // [5,576,64]
               const float* __restrict__ blk0_W,   // [5,64,64]
               const float* __restrict__ blk0_b,   // [5,64]
               const float* __restrict__ blk1_W,   // [5,64,64]
               const float* __restrict__ blk1_b,   // [5,64]
               const float* __restrict__ fc_out_W, // [64,12]
               const float* __restrict__ fc_out_b, // [12]
               float* __restrict__ out)            // [P,12]
{
    extern __shared__ char smraw[];
    float2* c_s   = (float2*)smraw;           // [64 k][64 pair]
    float2* act_s = c_s + 64*64;              // [64 k][64 pair]
    float*  w_s   = (float*)(act_s + 64*64);  // [64 k][64 j]
    float*  sm    = w_s + 64*64;              // small params

    const int tid   = threadIdx.x;
    const int px    = tid & 31;
    const int jy    = tid >> 5;
    const int jbase = jy * 8;
    const int base  = blockIdx.x * 128;       // first point of this tile

    // ---- phase 1: load small params ----
    for (int idx = tid; idx < SM_SMALL_N; idx += 256) {
        float v;
        if      (idx < 192)  v = fc_p_W[idx];
        else if (idx < 256)  v = fc_p_b[idx - 192];
        else if (idx < 576)  v = blk0_b[idx - 256];
        else if (idx < 896)  v = blk1_b[idx - 576];
        else if (idx < 1664) v = fc_out_W[idx - 896];
        else                 v = fc_out_b[idx - 1664];
        sm[idx] = v;
    }

    // ---- phase 1b: transposed packed c tile: c_s[k][pair] = {c[pt0][k], c[pt1][k]} ----
    #pragma unroll
    for (int pi = 0; pi < 2; ++pi) {
        int pair = px + 32*pi;
        int pt0 = base + 2*pair;
        const float4* c0 = (const float4*)(c + (size_t)pt0 * 64);
        const float4* c1 = (const float4*)(c + (size_t)(pt0 + 1) * 64);
        #pragma unroll
        for (int kq = 0; kq < 2; ++kq) {
            int kc = jy*2 + kq;               // 0..15 float4-chunks of k
            float4 u = c0[kc];
            float4 v = c1[kc];
            c_s[(4*kc + 0)*64 + pair] = make_float2(u.x, v.x);
            c_s[(4*kc + 1)*64 + pair] = make_float2(u.y, v.y);
            c_s[(4*kc + 2)*64 + pair] = make_float2(u.z, v.z);
            c_s[(4*kc + 3)*64 + pair] = make_float2(u.w, v.w);
        }
    }

    __syncthreads();

    // ---- net init: net = p @ fc_p_W + fc_p_b (K=3), kept in registers ----
    F2 net0[8], net1[8];
    #pragma unroll
    for (int pi = 0; pi < 2; ++pi) {
        int pair = px + 32*pi;
        int pt0 = base + 2*pair;
        F2 pp[3];
        #pragma unroll
        for (int d = 0; d < 3; ++d)
            pp[d].f = make_float2(p[(size_t)pt0*3 + d], p[(size_t)(pt0+1)*3 + d]);
        F2* nt = pi ? net1 : net0;
        #pragma unroll
        for (int jj = 0; jj < 8; ++jj) {
            int j = jbase + jj;
            F2 acc = dup2(sm[SM_BP + j]);
            #pragma unroll
            for (int d = 0; d < 3; ++d) {
                F2 wv = dup2(sm[SM_WP + d*64 + j]);
                ffma2(acc, pp[d], wv);
            }
            nt[jj] = acc;
        }
    }

    const int bA = (base + 2*px) / N_;          // batch of pair px  (pairs never straddle batches)
    const int bB = (base + 2*(px + 32)) / N_;   // batch of pair px+32

    F2 acc0[8], acc1[8];

    for (int i = 0; i < NB_; ++i) {
        // --- conditioning GEMM: net += c @ Wc[i][:64] + tfb[b][i] ---
        copy_w(w_s, fc_c_W + (size_t)i*CCD*H_, tid);     // rows 0..63 are contiguous
        __syncthreads();
        gemm64(c_s, w_s, px, jbase, acc0, acc1);
        __syncthreads();

        copy_w(w_s, blk0_W + (size_t)i*H_*H_, tid);
        #pragma unroll
        for (int jj = 0; jj < 8; ++jj) {
            int j = jbase + jj;
            float tA = g_tfb[(bA*NB_ + i)*H_ + j];
            float tB = g_tfb[(bB*NB_ + i)*H_ + j];
            net0[jj].f.x += acc0[jj].f.x + tA;
            net0[jj].f.y += acc0[jj].f.y + tA;
            net1[jj].f.x += acc1[jj].f.x + tB;
            net1[jj].f.y += acc1[jj].f.y + tB;
            act_s[j*64 + px]      = relu2(net0[jj]).f;
            act_s[j*64 + px + 32] = relu2(net1[jj]).f;
        }
        __syncthreads();

        // --- blk0: h = relu( relu(net) @ W0 + b0 ) ---
        gemm64(act_s, w_s, px, jbase, acc0, acc1);
        __syncthreads();

        copy_w(w_s, blk1_W + (size_t)i*H_*H_, tid);
        #pragma unroll
        for (int jj = 0; jj < 8; ++jj) {
            int j = jbase + jj;
            float b0v = sm[SM_B0 + i*64 + j];
            F2 h0, h1;
            h0.f.x = acc0[jj].f.x + b0v;  h0.f.y = acc0[jj].f.y + b0v;
            h1.f.x = acc1[jj].f.x + b0v;  h1.f.y = acc1[jj].f.y + b0v;
            act_s[j*64 + px]      = relu2(h0).f;
            act_s[j*64 + px + 32] = relu2(h1).f;
        }
        __syncthreads();

        // --- blk1: net += relu(h) @ W1 + b1 ---
        gemm64(act_s, w_s, px, jbase, acc0, acc1);
        __syncthreads();

        #pragma unroll
        for (int jj = 0; jj < 8; ++jj) {
            int j = jbase + jj;
            float b1v = sm[SM_B1 + i*64 + j];
            net0[jj].f.x += acc0[jj].f.x + b1v;
            net0[jj].f.y += acc0[jj].f.y + b1v;
            net1[jj].f.x += acc1[jj].f.x + b1v;
            net1[jj].f.y += acc1[jj].f.y + b1v;
        }
        if (i == NB_ - 1) {
            #pragma unroll
            for (int jj = 0; jj < 8; ++jj) {
                int j = jbase + jj;
                act_s[j*64 + px]      = relu2(net0[jj]).f;
                act_s[j*64 + px + 32] = relu2(net1[jj]).f;
            }
        }
    }
    __syncthreads();

    // ---- fc_out: out = relu(net) @ Wout + bout   (act_s holds relu(net)) ----
    if (jy < 6) {
        int o = jy * 2;
        F2 o00, o01, o10, o11;
        o00.u = 0ULL; o01.u = 0ULL; o10.u = 0ULL; o11.u = 0ULL;
        #pragma unroll 4
        for (int k = 0; k < 64; ++k) {
            F2 a0, a1;
            a0.f = act_s[k*64 + px];
            a1.f = act_s[k*64 + px + 32];
            F2 w0 = dup2(sm[SM_WOUT + k*12 + o]);
            F2 w1 = dup2(sm[SM_WOUT + k*12 + o + 1]);
            ffma2(o00, a0, w0);  ffma2(o01, a0, w1);
            ffma2(o10, a1, w0);  ffma2(o11, a1, w1);
        }
        float bo0 = sm[SM_BOUT + o], bo1 = sm[SM_BOUT + o + 1];
        int pt0 = base + 2*px;
        int pt2 = base + 2*(px + 32);
        out[(size_t)pt0*12 + o]         = o00.f.x + bo0;
        out[(size_t)(pt0+1)*12 + o]     = o00.f.y + bo0;
        out[(size_t)pt0*12 + o + 1]     = o01.f.x + bo1;
        out[(size_t)(pt0+1)*12 + o + 1] = o01.f.y + bo1;
        out[(size_t)pt2*12 + o]         = o10.f.x + bo0;
        out[(size_t)(pt2+1)*12 + o]     = o10.f.y + bo0;
        out[(size_t)pt2*12 + o + 1]     = o11.f.x + bo1;
        out[(size_t)(pt2+1)*12 + o + 1] = o11.f.y + bo1;
    }
}

extern "C" void kernel_launch(void* const* d_in, const int* in_sizes, int n_in,
                              void* d_out, int out_size)
{
    const float* p    = (const float*)d_in[0];
    const float* c    = (const float*)d_in[1];
    const float* task = (const float*)d_in[2];
    const float* fpW  = (const float*)d_in[3];
    const float* fpb  = (const float*)d_in[4];
    const float* fcW  = (const float*)d_in[5];
    const float* fcb  = (const float*)d_in[6];
    const float* b0W  = (const float*)d_in[7];
    const float* b0b  = (const float*)d_in[8];
    const float* b1W  = (const float*)d_in[9];
    const float* b1b  = (const float*)d_in[10];
    const float* foW  = (const float*)d_in[11];
    const float* fob  = (const float*)d_in[12];
    float* out = (float*)d_out;

    cudaFuncSetAttribute(decoder_kernel, cudaFuncAttributeMaxDynamicSharedMemorySize, SMEM_BYTES);

    tfb_kernel<<<B_*NB_, 64>>>(task, fcW, fcb);
    decoder_kernel<<<P_TOTAL/128, 256, SMEM_BYTES>>>(
        p, c, fpW, fpb, fcW, b0W, b0b, b1W, b1b, foW, fob, out);
}

// round 2
// speedup vs baseline: 1.0013x; 1.0013x over previous
#include <cuda_runtime.h>
#include <cstdint>

#define B_ 8
#define N_ 50000
#define P_TOTAL (B_*N_)     // 400000
#define H_ 64
#define CD 64
#define TD 512
#define NB_ 5
#define OUT_ 12
#define CCD (CD+TD)         // 576

// Precomputed task-feature contribution: tfb[b][i][j] = fc_c_b[i][j] + task[b] @ fc_c_W[i][64:,:]
__device__ float g_tfb[B_*NB_*H_];

// ---------------- packed f32x2 helpers ----------------
union F2 {
    float2 f;
    unsigned long long u;
};

__device__ __forceinline__ void ffma2(F2& d, const F2& a, const F2& b) {
    asm("fma.rn.f32x2 %0, %1, %2, %0;" : "+l"(d.u) : "l"(a.u), "l"(b.u));
}
__device__ __forceinline__ F2 dup2(float w) {
    F2 r; asm("mov.b64 %0, {%1, %1};" : "=l"(r.u) : "f"(w)); return r;
}
__device__ __forceinline__ F2 relu2(F2 v) {
    v.f.x = fmaxf(v.f.x, 0.f);
    v.f.y = fmaxf(v.f.y, 0.f);
    return v;
}

// ---------------- tfb precompute ----------------
__global__ void tfb_kernel(const float* __restrict__ task,   // [B,512]
                           const float* __restrict__ fcW,    // [NB,576,64]
                           const float* __restrict__ fcb)    // [NB,64]
{
    int blk = blockIdx.x;            // b*NB + i
    int b = blk / NB_, i = blk % NB_;
    int j = threadIdx.x;
    float acc = fcb[i*H_ + j];
    const float* w = fcW + ((size_t)i*CCD + CD)*H_ + j;
    const float* t = task + (size_t)b*TD;
    #pragma unroll 8
    for (int k = 0; k < TD; ++k)
        acc += t[k] * w[(size_t)k*H_];
    g_tfb[(b*NB_ + i)*H_ + j] = acc;
}

// ---------------- main kernel ----------------
// SMEM small-param offsets (floats)
#define SM_WP   0        // fc_p_W [3][64]
#define SM_BP   192      // fc_p_b [64]
#define SM_B0   256      // blk0_b [5][64]
#define SM_B1   576      // blk1_b [5][64]
#define SM_WOUT 896      // fc_out_W [64][12]
#define SM_BOUT 1664     // fc_out_b [12]
#define SM_SMALL_N 1676

#define SMEM_BYTES (64*64*8 /*c_s*/ + 64*64*8 /*act_s*/ + 64*64*4 /*w_s*/ + SM_SMALL_N*4)

// Copy one 64x64 fp32 weight matrix (k-major, same as global layout) into w_s.
__device__ __forceinline__ void copy_w(float* w_s, const float* __restrict__ src, int tid) {
    const float4* s4 = (const float4*)src;
    float4* d4 = (float4*)w_s;
    #pragma unroll
    for (int r = 0; r < 4; ++r)
        d4[tid + 256*r] = s4[tid + 256*r];
}

// One 128pts x 64out x 64k GEMM. Input activations packed [k][pair] float2 in smem.
// Thread accumulates 8 outputs for pairs px (acc0) and px+32 (acc1).
__device__ __forceinline__ void gemm64(const float2* __restrict__ in, const float* __restrict__ w,
                                       int px, int jbase, F2 acc0[8], F2 acc1[8])
{
    #pragma unroll
    for (int jj = 0; jj < 8; ++jj) { acc0[jj].u = 0ULL; acc1[jj].u = 0ULL; }
    #pragma unroll 4
    for (int k = 0; k < 64; ++k) {
        F2 a0, a1;
        a0.f = in[k*64 + px];
        a1.f = in[k*64 + px + 32];
        const float4* wr = (const float4*)(w + k*64 + jbase);  // warp-uniform -> LDS broadcast
        float4 w0 = wr[0], w1 = wr[1];
        F2 pk;
        pk = dup2(w0.x); ffma2(acc0[0], a0, pk); ffma2(acc1[0], a1, pk);
        pk = dup2(w0.y); ffma2(acc0[1], a0, pk); ffma2(acc1[1], a1, pk);
        pk = dup2(w0.z); ffma2(acc0[2], a0, pk); ffma2(acc1[2], a1, pk);
        pk = dup2(w0.w); ffma2(acc0[3], a0, pk); ffma2(acc1[3], a1, pk);
        pk = dup2(w1.x); ffma2(acc0[4], a0, pk); ffma2(acc1[4], a1, pk);
        pk = dup2(w1.y); ffma2(acc0[5], a0, pk); ffma2(acc1[5], a1, pk);
        pk = dup2(w1.z); ffma2(acc0[6], a0, pk); ffma2(acc1[6], a1, pk);
        pk = dup2(w1.w); ffma2(acc0[7], a0, pk); ffma2(acc1[7], a1, pk);
    }
}

__global__ void __launch_bounds__(256, 2)
decoder_kernel(const float* __restrict__ p,        // [P,3]
               const float* __restrict__ c,        // [P,64]
               const float* __restrict__ fc_p_W,   // [3,64]
               const float* __restrict__ fc_p_b,   // [64]
               const float* __restrict__ fc_c_W,   // [5,576,64]
               const float* __restrict__ blk0_W,   // [5,64,64]
               const float* __restrict__ blk0_b,   // [5,64]
               const float* __restrict__ blk1_W,   // [5,64,64]
               const float* __restrict__ blk1_b,   // [5,64]
               const float* __restrict__ fc_out_W, // [64,12]
               const float* __restrict__ fc_out_b, // [12]
               float* __restrict__ out)            // [P,12]
{
    extern __shared__ char smraw[];
    float2* c_s   = (float2*)smraw;           // [64 k][64 pair]
    float2* act_s = c_s + 64*64;              // [64 k][64 pair]
    float*  w_s   = (float*)(act_s + 64*64);  // [64 k][64 j]
    float*  sm    = w_s + 64*64;              // small params

    const int tid   = threadIdx.x;
    const int px    = tid & 31;
    const int jy    = tid >> 5;
    const int jbase = jy * 8;
    const int base  = blockIdx.x * 128;       // first point of this tile

    // ---- phase 1: load small params ----
    for (int idx = tid; idx < SM_SMALL_N; idx += 256) {
        float v;
        if      (idx < 192)  v = fc_p_W[idx];
        else if (idx < 256)  v = fc_p_b[idx - 192];
        else if (idx < 576)  v = blk0_b[idx - 256];
        else if (idx < 896)  v = blk1_b[idx - 576];
        else if (idx < 1664) v = fc_out_W[idx - 896];
        else                 v = fc_out_b[idx - 1664];
        sm[idx] = v;
    }

    // ---- phase 1b: transposed packed c tile: c_s[k][pair] = {c[pt0][k], c[pt1][k]} ----
    #pragma unroll
    for (int pi = 0; pi < 2; ++pi) {
        int pair = px + 32*pi;
        int pt0 = base + 2*pair;
        const float4* c0 = (const float4*)(c + (size_t)pt0 * 64);
        const float4* c1 = (const float4*)(c + (size_t)(pt0 + 1) * 64);
        #pragma unroll
        for (int kq = 0; kq < 2; ++kq) {
            int kc = jy*2 + kq;               // 0..15 float4-chunks of k
            float4 u = c0[kc];
            float4 v = c1[kc];
            c_s[(4*kc + 0)*64 + pair] = make_float2(u.x, v.x);
            c_s[(4*kc + 1)*64 + pair] = make_float2(u.y, v.y);
            c_s[(4*kc + 2)*64 + pair] = make_float2(u.z, v.z);
            c_s[(4*kc + 3)*64 + pair] = make_float2(u.w, v.w);
        }
    }

    __syncthreads();

    // ---- net init: net = p @ fc_p_W + fc_p_b (K=3), kept in registers ----
    F2 net0[8], net1[8];
    #pragma unroll
    for (int pi = 0; pi < 2; ++pi) {
        int pair = px + 32*pi;
        int pt0 = base + 2*pair;
        F2 pp[3];
        #pragma unroll
        for (int d = 0; d < 3; ++d)
            pp[d].f = make_float2(p[(size_t)pt0*3 + d], p[(size_t)(pt0+1)*3 + d]);
        F2* nt = pi ? net1 : net0;
        #pragma unroll
        for (int jj = 0; jj < 8; ++jj) {
            int j = jbase + jj;
            F2 acc = dup2(sm[SM_BP + j]);
            #pragma unroll
            for (int d = 0; d < 3; ++d) {
                F2 wv = dup2(sm[SM_WP + d*64 + j]);
                ffma2(acc, pp[d], wv);
            }
            nt[jj] = acc;
        }
    }

    const int bA = (base + 2*px) / N_;          // batch of pair px  (pairs never straddle batches)
    const int bB = (base + 2*(px + 32)) / N_;   // batch of pair px+32

    F2 acc0[8], acc1[8];

    for (int i = 0; i < NB_; ++i) {
        // --- conditioning GEMM: net += c @ Wc[i][:64] + tfb[b][i] ---
        copy_w(w_s, fc_c_W + (size_t)i*CCD*H_, tid);     // rows 0..63 are contiguous
        __syncthreads();
        gemm64(c_s, w_s, px, jbase, acc0, acc1);
        __syncthreads();

        copy_w(w_s, blk0_W + (size_t)i*H_*H_, tid);
        #pragma unroll
        for (int jj = 0; jj < 8; ++jj) {
            int j = jbase + jj;
            float tA = g_tfb[(bA*NB_ + i)*H_ + j];
            float tB = g_tfb[(bB*NB_ + i)*H_ + j];
            net0[jj].f.x += acc0[jj].f.x + tA;
            net0[jj].f.y += acc0[jj].f.y + tA;
            net1[jj].f.x += acc1[jj].f.x + tB;
            net1[jj].f.y += acc1[jj].f.y + tB;
            act_s[j*64 + px]      = relu2(net0[jj]).f;
            act_s[j*64 + px + 32] = relu2(net1[jj]).f;
        }
        __syncthreads();

        // --- blk0: h = relu( relu(net) @ W0 + b0 ) ---
        gemm64(act_s, w_s, px, jbase, acc0, acc1);
        __syncthreads();

        copy_w(w_s, blk1_W + (size_t)i*H_*H_, tid);
        #pragma unroll
        for (int jj = 0; jj < 8; ++jj) {
            int j = jbase + jj;
            float b0v = sm[SM_B0 + i*64 + j];
            F2 h0, h1;
            h0.f.x = acc0[jj].f.x + b0v;  h0.f.y = acc0[jj].f.y + b0v;
            h1.f.x = acc1[jj].f.x + b0v;  h1.f.y = acc1[jj].f.y + b0v;
            act_s[j*64 + px]      = relu2(h0).f;
            act_s[j*64 + px + 32] = relu2(h1).f;
        }
        __syncthreads();

        // --- blk1: net += relu(h) @ W1 + b1 ---
        gemm64(act_s, w_s, px, jbase, acc0, acc1);
        __syncthreads();

        #pragma unroll
        for (int jj = 0; jj < 8; ++jj) {
            int j = jbase + jj;
            float b1v = sm[SM_B1 + i*64 + j];
            net0[jj].f.x += acc0[jj].f.x + b1v;
            net0[jj].f.y += acc0[jj].f.y + b1v;
            net1[jj].f.x += acc1[jj].f.x + b1v;
            net1[jj].f.y += acc1[jj].f.y + b1v;
        }
        if (i == NB_ - 1) {
            #pragma unroll
            for (int jj = 0; jj < 8; ++jj) {
                int j = jbase + jj;
                act_s[j*64 + px]      = relu2(net0[jj]).f;
                act_s[j*64 + px + 32] = relu2(net1[jj]).f;
            }
        }
    }
    __syncthreads();

    // ---- fc_out: out = relu(net) @ Wout + bout   (act_s holds relu(net)) ----
    if (jy < 6) {
        int o = jy * 2;
        F2 o00, o01, o10, o11;
        o00.u = 0ULL; o01.u = 0ULL; o10.u = 0ULL; o11.u = 0ULL;
        #pragma unroll 4
        for (int k = 0; k < 64; ++k) {
            F2 a0, a1;
            a0.f = act_s[k*64 + px];
            a1.f = act_s[k*64 + px + 32];
            F2 w0 = dup2(sm[SM_WOUT + k*12 + o]);
            F2 w1 = dup2(sm[SM_WOUT + k*12 + o + 1]);
            ffma2(o00, a0, w0);  ffma2(o01, a0, w1);
            ffma2(o10, a1, w0);  ffma2(o11, a1, w1);
        }
        float bo0 = sm[SM_BOUT + o], bo1 = sm[SM_BOUT + o + 1];
        int pt0 = base + 2*px;
        int pt2 = base + 2*(px + 32);
        out[(size_t)pt0*12 + o]         = o00.f.x + bo0;
        out[(size_t)(pt0+1)*12 + o]     = o00.f.y + bo0;
        out[(size_t)pt0*12 + o + 1]     = o01.f.x + bo1;
        out[(size_t)(pt0+1)*12 + o + 1] = o01.f.y + bo1;
        out[(size_t)pt2*12 + o]         = o10.f.x + bo0;
        out[(size_t)(pt2+1)*12 + o]     = o10.f.y + bo0;
        out[(size_t)pt2*12 + o + 1]     = o11.f.x + bo1;
        out[(size_t)(pt2+1)*12 + o + 1] = o11.f.y + bo1;
    }
}

extern "C" void kernel_launch(void* const* d_in, const int* in_sizes, int n_in,
                              void* d_out, int out_size)
{
    const float* p    = (const float*)d_in[0];
    const float* c    = (const float*)d_in[1];
    const float* task = (const float*)d_in[2];
    const float* fpW  = (const float*)d_in[3];
    const float* fpb  = (const float*)d_in[4];
    const float* fcW  = (const float*)d_in[5];
    const float* fcb  = (const float*)d_in[6];
    const float* b0W  = (const float*)d_in[7];
    const float* b0b  = (const float*)d_in[8];
    const float* b1W  = (const float*)d_in[9];
    const float* b1b  = (const float*)d_in[10];
    const float* foW  = (const float*)d_in[11];
    const float* fob  = (const float*)d_in[12];
    float* out = (float*)d_out;

    cudaFuncSetAttribute(decoder_kernel, cudaFuncAttributeMaxDynamicSharedMemorySize, SMEM_BYTES);

    tfb_kernel<<<B_*NB_, 64>>>(task, fcW, fcb);
    decoder_kernel<<<P_TOTAL/128, 256, SMEM_BYTES>>>(
        p, c, fpW, fpb, fcW, b0W, b0b, b1W, b1b, foW, fob, out);
}